// round 2
// baseline (speedup 1.0000x reference)
#include <cuda_runtime.h>

// Problem dims (fixed)
#define BATCH  4
#define SEQ    2048
#define DMODEL 1024
#define NHEAD  16
#define HDIM   64
#define MROWS  (BATCH*SEQ)   // 8192

// Scratch (device-static: allocation-free per harness rules)
__device__ float g_q[(size_t)MROWS*DMODEL];
__device__ float g_k[(size_t)MROWS*DMODEL];
__device__ float g_v[(size_t)MROWS*DMODEL];
__device__ float g_o[(size_t)MROWS*DMODEL];
__device__ float g_y[(size_t)MROWS*DMODEL];

// ---------------------------------------------------------------------------
// GEMM: C[M,N] = A[M,K] @ B[K,N]  (+ optional bias[N] + optional resid[M,N])
// 128x128 block tile, BK=8, 256 threads, 8x8 per-thread register tile.
// ---------------------------------------------------------------------------
#define GBM 128
#define GBN 128
#define GBK 8

__global__ __launch_bounds__(256)
void gemm_kernel(const float* __restrict__ A, const float* __restrict__ B,
                 float* __restrict__ C, const float* __restrict__ bias,
                 const float* __restrict__ resid, int M, int N, int K)
{
    __shared__ float As[GBK][GBM];
    __shared__ float Bs[GBK][GBN];

    const int t  = threadIdx.x;
    const int tx = t & 15;
    const int ty = t >> 4;
    const int bm = blockIdx.y * GBM;
    const int bn = blockIdx.x * GBN;

    const int arow = t >> 1;          // 0..127
    const int acol = (t & 1) * 4;     // 0 or 4
    const int brow = t >> 5;          // 0..7
    const int bcol = (t & 31) * 4;    // 0..124

    float acc[8][8];
#pragma unroll
    for (int i = 0; i < 8; i++)
#pragma unroll
        for (int j = 0; j < 8; j++) acc[i][j] = 0.f;

    const float* Aptr = A + (size_t)(bm + arow) * K + acol;
    const float* Bptr = B + (size_t)brow * N + bn + bcol;

    for (int k0 = 0; k0 < K; k0 += GBK) {
        float4 av = *(const float4*)(Aptr + k0);
        As[acol + 0][arow] = av.x;
        As[acol + 1][arow] = av.y;
        As[acol + 2][arow] = av.z;
        As[acol + 3][arow] = av.w;
        float4 bv = *(const float4*)(Bptr + (size_t)k0 * N);
        *(float4*)&Bs[brow][bcol] = bv;
        __syncthreads();
#pragma unroll
        for (int kk = 0; kk < GBK; kk++) {
            float a[8], b[8];
#pragma unroll
            for (int i = 0; i < 8; i++) a[i] = As[kk][ty * 8 + i];
#pragma unroll
            for (int j = 0; j < 8; j++) b[j] = Bs[kk][tx * 8 + j];
#pragma unroll
            for (int i = 0; i < 8; i++)
#pragma unroll
                for (int j = 0; j < 8; j++)
                    acc[i][j] = fmaf(a[i], b[j], acc[i][j]);
        }
        __syncthreads();
    }

#pragma unroll
    for (int i = 0; i < 8; i++) {
        int row = bm + ty * 8 + i;
#pragma unroll
        for (int j = 0; j < 8; j += 4) {
            int col = bn + tx * 8 + j;
            float4 r = make_float4(acc[i][j], acc[i][j+1], acc[i][j+2], acc[i][j+3]);
            if (bias) {
                float4 bb = *(const float4*)(bias + col);
                r.x += bb.x; r.y += bb.y; r.z += bb.z; r.w += bb.w;
            }
            if (resid) {
                float4 xv = *(const float4*)(resid + (size_t)row * N + col);
                r.x += xv.x; r.y += xv.y; r.z += xv.z; r.w += xv.w;
            }
            *(float4*)(C + (size_t)row * N + col) = r;
        }
    }
}

// ---------------------------------------------------------------------------
// Flash attention (fp32, online softmax).
// Grid: (SEQ/64, NHEAD, BATCH); 128 threads/block.
// Q tile 64x64 resident; stream K/V in 32-row tiles.
// Q/K/V/O layout: [B*S, NHEAD*HDIM] row-major (GEMM-natural).
// ---------------------------------------------------------------------------
#define AQ  64
#define AKV 32

__global__ __launch_bounds__(128)
void attn_kernel(const float* __restrict__ Q, const float* __restrict__ K,
                 const float* __restrict__ V, float* __restrict__ O)
{
    __shared__ float Qs[AQ][HDIM + 1];
    __shared__ float Ks[AKV][HDIM + 1];
    __shared__ float Vs[AKV][HDIM + 1];
    __shared__ float Ps[AQ][AKV + 1];
    __shared__ float m_s[AQ], l_s[AQ], al_s[AQ];

    const int t  = threadIdx.x;
    const int b  = blockIdx.z;
    const int h  = blockIdx.y;
    const int q0 = blockIdx.x * AQ;
    const size_t base = (size_t)b * SEQ * DMODEL + (size_t)h * HDIM;

    // Load Q tile (64 rows x 64 floats)
    for (int i = t; i < AQ * (HDIM / 4); i += 128) {
        int r = i >> 4;
        int c = (i & 15) << 2;
        float4 qv = *(const float4*)(Q + base + (size_t)(q0 + r) * DMODEL + c);
        Qs[r][c] = qv.x; Qs[r][c+1] = qv.y; Qs[r][c+2] = qv.z; Qs[r][c+3] = qv.w;
    }
    if (t < AQ) { m_s[t] = -1e30f; l_s[t] = 0.f; }

    const int rg  = t & 15;     // row group
    const int grp = t >> 4;     // 0..7
    const int r0  = rg * 4;     // 4 q-rows per thread
    const int j0  = grp * 4;    // phase-1: 4 keys per thread
    const int d0  = grp * 8;    // phase-3: 8 out-dims per thread

    float o[4][8];
#pragma unroll
    for (int i = 0; i < 4; i++)
#pragma unroll
        for (int d = 0; d < 8; d++) o[i][d] = 0.f;

    __syncthreads();

    for (int kv0 = 0; kv0 < SEQ; kv0 += AKV) {
        // Load K,V tiles (32 x 64 each)
        for (int i = t; i < AKV * (HDIM / 4); i += 128) {
            int r = i >> 4;
            int c = (i & 15) << 2;
            float4 kv = *(const float4*)(K + base + (size_t)(kv0 + r) * DMODEL + c);
            Ks[r][c] = kv.x; Ks[r][c+1] = kv.y; Ks[r][c+2] = kv.z; Ks[r][c+3] = kv.w;
            float4 vv = *(const float4*)(V + base + (size_t)(kv0 + r) * DMODEL + c);
            Vs[r][c] = vv.x; Vs[r][c+1] = vv.y; Vs[r][c+2] = vv.z; Vs[r][c+3] = vv.w;
        }
        __syncthreads();

        // Phase 1: logits S = Q Kt  (64x32), 4x4 micro-tile per thread
        float s[4][4];
#pragma unroll
        for (int i = 0; i < 4; i++)
#pragma unroll
            for (int j = 0; j < 4; j++) s[i][j] = 0.f;
#pragma unroll 8
        for (int d = 0; d < HDIM; d++) {
            float qv[4], kvv[4];
#pragma unroll
            for (int i = 0; i < 4; i++) qv[i] = Qs[r0 + i][d];
#pragma unroll
            for (int j = 0; j < 4; j++) kvv[j] = Ks[j0 + j][d];
#pragma unroll
            for (int i = 0; i < 4; i++)
#pragma unroll
                for (int j = 0; j < 4; j++)
                    s[i][j] = fmaf(qv[i], kvv[j], s[i][j]);
        }
#pragma unroll
        for (int i = 0; i < 4; i++)
#pragma unroll
            for (int j = 0; j < 4; j++)
                Ps[r0 + i][j0 + j] = s[i][j] * 0.125f;   // * HEAD_DIM^-0.5
        __syncthreads();

        // Phase 2: online softmax stats, one thread per row
        if (t < AQ) {
            float mold = m_s[t];
            float mx = mold;
#pragma unroll
            for (int j = 0; j < AKV; j++) mx = fmaxf(mx, Ps[t][j]);
            float lsum = 0.f;
#pragma unroll
            for (int j = 0; j < AKV; j++) {
                float p = __expf(Ps[t][j] - mx);
                Ps[t][j] = p;
                lsum += p;
            }
            float alpha = __expf(mold - mx);
            m_s[t] = mx;
            l_s[t] = l_s[t] * alpha + lsum;
            al_s[t] = alpha;
        }
        __syncthreads();

        // Phase 3: O += P @ V, 4x8 micro-tile per thread
        float al[4];
#pragma unroll
        for (int i = 0; i < 4; i++) al[i] = al_s[r0 + i];
#pragma unroll
        for (int i = 0; i < 4; i++)
#pragma unroll
            for (int d = 0; d < 8; d++) o[i][d] *= al[i];
#pragma unroll 4
        for (int j = 0; j < AKV; j++) {
            float p[4], vv[8];
#pragma unroll
            for (int i = 0; i < 4; i++) p[i] = Ps[r0 + i][j];
#pragma unroll
            for (int d = 0; d < 8; d++) vv[d] = Vs[j][d0 + d];
#pragma unroll
            for (int i = 0; i < 4; i++)
#pragma unroll
                for (int d = 0; d < 8; d++)
                    o[i][d] = fmaf(p[i], vv[d], o[i][d]);
        }
        __syncthreads();
    }

    // Write out (normalize by l)
#pragma unroll
    for (int i = 0; i < 4; i++) {
        float inv = 1.f / l_s[r0 + i];
        float4 v0 = make_float4(o[i][0]*inv, o[i][1]*inv, o[i][2]*inv, o[i][3]*inv);
        float4 v1 = make_float4(o[i][4]*inv, o[i][5]*inv, o[i][6]*inv, o[i][7]*inv);
        float* op = O + base + (size_t)(q0 + r0 + i) * DMODEL + d0;
        *(float4*)op       = v0;
        *(float4*)(op + 4) = v1;
    }
}

// ---------------------------------------------------------------------------
// LayerNorm: one block per row (1024 elems), 256 threads, eps = 1e-6
// ---------------------------------------------------------------------------
__global__ __launch_bounds__(256)
void ln_kernel(const float* __restrict__ Y, const float* __restrict__ gamma,
               const float* __restrict__ beta, float* __restrict__ out)
{
    const int row = blockIdx.x;
    const int t = threadIdx.x;
    const float* y = Y + (size_t)row * DMODEL;

    float4 v = *(const float4*)(y + t * 4);
    float s  = v.x + v.y + v.z + v.w;
    float ss = v.x*v.x + v.y*v.y + v.z*v.z + v.w*v.w;

    __shared__ float rs[8], rss[8];
    int lane = t & 31, wid = t >> 5;
#pragma unroll
    for (int o = 16; o > 0; o >>= 1) {
        s  += __shfl_xor_sync(0xffffffffu, s,  o);
        ss += __shfl_xor_sync(0xffffffffu, ss, o);
    }
    if (lane == 0) { rs[wid] = s; rss[wid] = ss; }
    __syncthreads();
    if (wid == 0) {
        s  = (lane < 8) ? rs[lane]  : 0.f;
        ss = (lane < 8) ? rss[lane] : 0.f;
#pragma unroll
        for (int o = 4; o > 0; o >>= 1) {
            s  += __shfl_xor_sync(0xffffffffu, s,  o);
            ss += __shfl_xor_sync(0xffffffffu, ss, o);
        }
        if (lane == 0) { rs[0] = s; rss[0] = ss; }
    }
    __syncthreads();

    float mean = rs[0] * (1.f / DMODEL);
    float var  = rss[0] * (1.f / DMODEL) - mean * mean;
    float rstd = rsqrtf(var + 1e-6f);

    float4 g  = *(const float4*)(gamma + t * 4);
    float4 be = *(const float4*)(beta  + t * 4);
    float4 r;
    r.x = (v.x - mean) * rstd * g.x + be.x;
    r.y = (v.y - mean) * rstd * g.y + be.y;
    r.z = (v.z - mean) * rstd * g.z + be.z;
    r.w = (v.w - mean) * rstd * g.w + be.w;
    *(float4*)(out + (size_t)row * DMODEL + t * 4) = r;
}

// ---------------------------------------------------------------------------
// Launch
// ---------------------------------------------------------------------------
extern "C" void kernel_launch(void* const* d_in, const int* in_sizes, int n_in,
                              void* d_out, int out_size)
{
    const float* x      = (const float*)d_in[0];
    const float* w_q    = (const float*)d_in[1];
    const float* w_k    = (const float*)d_in[2];
    const float* w_v    = (const float*)d_in[3];
    const float* w_proj = (const float*)d_in[4];
    const float* b_proj = (const float*)d_in[5];
    const float* gamma  = (const float*)d_in[6];
    const float* beta   = (const float*)d_in[7];
    float* out = (float*)d_out;

    float *q, *k, *v, *o, *y;
    cudaGetSymbolAddress((void**)&q, g_q);
    cudaGetSymbolAddress((void**)&k, g_k);
    cudaGetSymbolAddress((void**)&v, g_v);
    cudaGetSymbolAddress((void**)&o, g_o);
    cudaGetSymbolAddress((void**)&y, g_y);

    dim3 gg(DMODEL / GBN, MROWS / GBM);   // (8, 64)
    gemm_kernel<<<gg, 256>>>(x, w_q, q, nullptr, nullptr, MROWS, DMODEL, DMODEL);
    gemm_kernel<<<gg, 256>>>(x, w_k, k, nullptr, nullptr, MROWS, DMODEL, DMODEL);
    gemm_kernel<<<gg, 256>>>(x, w_v, v, nullptr, nullptr, MROWS, DMODEL, DMODEL);

    dim3 ga(SEQ / AQ, NHEAD, BATCH);      // (32, 16, 4)
    attn_kernel<<<ga, 128>>>(q, k, v, o);

    gemm_kernel<<<gg, 256>>>(o, w_proj, y, b_proj, x, MROWS, DMODEL, DMODEL);

    ln_kernel<<<MROWS, 256>>>(y, gamma, beta, out);
}

// round 4
// speedup vs baseline: 1.6942x; 1.6942x over previous
#include <cuda_runtime.h>
#include <cuda_bf16.h>
#include <cstdint>

// Problem dims (fixed)
#define BATCH  4
#define SEQ    2048
#define DMODEL 1024
#define NHEAD  16
#define HDIM   64
#define MROWS  (BATCH*SEQ)   // 8192

// ---------------------------------------------------------------------------
// Scratch (device-static: allocation-free per harness rules)
// ---------------------------------------------------------------------------
__device__ float g_q[(size_t)MROWS*DMODEL];
__device__ float g_k[(size_t)MROWS*DMODEL];
__device__ float g_v[(size_t)MROWS*DMODEL];
__device__ float g_o[(size_t)MROWS*DMODEL];
__device__ float g_y[(size_t)MROWS*DMODEL];
__device__ __nv_bfloat16 g_xb[(size_t)MROWS*DMODEL];
__device__ __nv_bfloat16 g_ob[(size_t)MROWS*DMODEL];
__device__ __nv_bfloat16 g_wqb[(size_t)DMODEL*DMODEL];
__device__ __nv_bfloat16 g_wkb[(size_t)DMODEL*DMODEL];
__device__ __nv_bfloat16 g_wvb[(size_t)DMODEL*DMODEL];
__device__ __nv_bfloat16 g_wpb[(size_t)DMODEL*DMODEL];

// ---------------------------------------------------------------------------
// PTX helpers (base ISA only — sm_103 target has no tcgen05)
// ---------------------------------------------------------------------------
__device__ __forceinline__ uint32_t smem_u32(const void* p) {
    uint32_t a;
    asm("{ .reg .u64 t; cvta.to.shared.u64 t, %1; cvt.u32.u64 %0, t; }" : "=r"(a) : "l"(p));
    return a;
}
#define CP_ASYNC16(dst, src) \
    asm volatile("cp.async.cg.shared.global [%0], [%1], 16;" :: "r"(dst), "l"(src))
#define CP_COMMIT()   asm volatile("cp.async.commit_group;")
#define CP_WAIT(N)    asm volatile("cp.async.wait_group %0;" :: "n"(N))

__device__ __forceinline__ void ldmx4(uint32_t addr, uint32_t& r0, uint32_t& r1,
                                      uint32_t& r2, uint32_t& r3) {
    asm volatile("ldmatrix.sync.aligned.m8n8.x4.shared.b16 {%0,%1,%2,%3}, [%4];"
                 : "=r"(r0), "=r"(r1), "=r"(r2), "=r"(r3) : "r"(addr));
}
__device__ __forceinline__ void mma_bf16(float c[4], uint32_t a0, uint32_t a1,
                                         uint32_t a2, uint32_t a3,
                                         uint32_t b0, uint32_t b1) {
    asm volatile("mma.sync.aligned.m16n8k16.row.col.f32.bf16.bf16.f32 "
                 "{%0,%1,%2,%3}, {%4,%5,%6,%7}, {%8,%9}, {%0,%1,%2,%3};"
                 : "+f"(c[0]), "+f"(c[1]), "+f"(c[2]), "+f"(c[3])
                 : "r"(a0), "r"(a1), "r"(a2), "r"(a3), "r"(b0), "r"(b1));
}

// ---------------------------------------------------------------------------
// bf16 mma.sync GEMM: C[M,N] = A[M,K] @ Bt[N,K]^T   (fp32 accumulate/output)
// 128x128 tile, BK=32, 256 threads (2x4 warps, 64x32 warp tile), cp.async
// double-buffered. Optional epilogue: + bias[N] + resid[M,N].
// ---------------------------------------------------------------------------
#define BM  128
#define BN  128
#define BKK 32
#define STR 40                       // smem row stride (bf16) => 80B, ldmatrix conflict-free
#define NITER (DMODEL / BKK)         // 32

__global__ __launch_bounds__(256)
void gemm_mma(const __nv_bfloat16* __restrict__ A, const __nv_bfloat16* __restrict__ Bt,
              float* __restrict__ C, const float* __restrict__ bias,
              const float* __restrict__ resid)
{
    __shared__ __nv_bfloat16 As[2][BM * STR];
    __shared__ __nv_bfloat16 Bs[2][BM * STR];

    const int t    = threadIdx.x;
    const int lane = t & 31;
    const int warp = t >> 5;
    const int wm   = (warp >> 2) * 64;   // 0 or 64
    const int wn   = (warp & 3) * 32;    // 0,32,64,96
    const int bm   = blockIdx.y * BM;
    const int bn   = blockIdx.x * BN;

    // global-load mapping: each thread: 2 A rows + 2 B rows, 16B each
    const int lr = t >> 2;               // 0..63
    const int lc = (t & 3) * 8;          // bf16 col offset within BK

    const __nv_bfloat16* a0 = A  + (size_t)(bm + lr) * DMODEL + lc;
    const __nv_bfloat16* a1 = A  + (size_t)(bm + lr + 64) * DMODEL + lc;
    const __nv_bfloat16* b0 = Bt + (size_t)(bn + lr) * DMODEL + lc;
    const __nv_bfloat16* b1 = Bt + (size_t)(bn + lr + 64) * DMODEL + lc;

    const uint32_t sA = smem_u32(As);
    const uint32_t sB = smem_u32(Bs);
    const uint32_t dA0 = sA + (uint32_t)(lr * STR + lc) * 2;
    const uint32_t dA1 = sA + (uint32_t)((lr + 64) * STR + lc) * 2;
    const uint32_t dB0 = sB + (uint32_t)(lr * STR + lc) * 2;
    const uint32_t dB1 = sB + (uint32_t)((lr + 64) * STR + lc) * 2;
    const uint32_t sbuf = BM * STR * 2;  // bytes per buffer

    float acc[4][4][4];
#pragma unroll
    for (int i = 0; i < 4; i++)
#pragma unroll
        for (int j = 0; j < 4; j++)
#pragma unroll
            for (int e = 0; e < 4; e++) acc[i][j][e] = 0.f;

    // prologue: tile 0 -> buffer 0
    CP_ASYNC16(dA0, a0); CP_ASYNC16(dA1, a1);
    CP_ASYNC16(dB0, b0); CP_ASYNC16(dB1, b1);
    CP_COMMIT();

    // ldmatrix lane addressing (within current buffer)
    const uint32_t aoff = (uint32_t)((wm + (lane & 15)) * STR + ((lane >> 4) << 3)) * 2;
    const uint32_t boff = (uint32_t)((wn + ((lane >> 4) << 3) + (lane & 7)) * STR
                                     + (((lane >> 3) & 1) << 3)) * 2;

    for (int it = 0; it < NITER; it++) {
        const int s = it & 1;
        if (it + 1 < NITER) {
            const int koff = (it + 1) * BKK;
            const uint32_t bo = (uint32_t)((it + 1) & 1) * sbuf;
            CP_ASYNC16(dA0 + bo, a0 + koff); CP_ASYNC16(dA1 + bo, a1 + koff);
            CP_ASYNC16(dB0 + bo, b0 + koff); CP_ASYNC16(dB1 + bo, b1 + koff);
            CP_COMMIT();
            CP_WAIT(1);
        } else {
            CP_WAIT(0);
        }
        __syncthreads();

        const uint32_t base = (uint32_t)s * sbuf;
#pragma unroll
        for (int kh = 0; kh < 2; kh++) {
            uint32_t a[4][4], bfr[4][2];
#pragma unroll
            for (int mi = 0; mi < 4; mi++) {
                uint32_t addr = sA + base + aoff + (uint32_t)(mi * 16 * STR + kh * 16) * 2;
                ldmx4(addr, a[mi][0], a[mi][1], a[mi][2], a[mi][3]);
            }
#pragma unroll
            for (int j = 0; j < 2; j++) {
                uint32_t addr = sB + base + boff + (uint32_t)(j * 16 * STR + kh * 16) * 2;
                uint32_t r0, r1, r2, r3;
                ldmx4(addr, r0, r1, r2, r3);
                bfr[j*2][0] = r0; bfr[j*2][1] = r1;
                bfr[j*2+1][0] = r2; bfr[j*2+1][1] = r3;
            }
#pragma unroll
            for (int mi = 0; mi < 4; mi++)
#pragma unroll
                for (int ni = 0; ni < 4; ni++)
                    mma_bf16(acc[mi][ni], a[mi][0], a[mi][1], a[mi][2], a[mi][3],
                             bfr[ni][0], bfr[ni][1]);
        }
        __syncthreads();
    }

    // epilogue
    const int r0 = bm + wm + (lane >> 2);
    const int c0 = bn + wn + (lane & 3) * 2;
#pragma unroll
    for (int mi = 0; mi < 4; mi++) {
#pragma unroll
        for (int ni = 0; ni < 4; ni++) {
            const int row = r0 + mi * 16;
            const int col = c0 + ni * 8;
            float2 v0 = make_float2(acc[mi][ni][0], acc[mi][ni][1]);
            float2 v1 = make_float2(acc[mi][ni][2], acc[mi][ni][3]);
            if (bias) {
                const float2 bb = *(const float2*)(bias + col);
                v0.x += bb.x; v0.y += bb.y; v1.x += bb.x; v1.y += bb.y;
            }
            if (resid) {
                const float2 x0 = *(const float2*)(resid + (size_t)row * DMODEL + col);
                const float2 x1 = *(const float2*)(resid + (size_t)(row + 8) * DMODEL + col);
                v0.x += x0.x; v0.y += x0.y; v1.x += x1.x; v1.y += x1.y;
            }
            *(float2*)(C + (size_t)row * DMODEL + col)       = v0;
            *(float2*)(C + (size_t)(row + 8) * DMODEL + col) = v1;
        }
    }
}

// ---------------------------------------------------------------------------
// fp32 -> bf16 cast (elementwise, vectorized)
// ---------------------------------------------------------------------------
__global__ __launch_bounds__(256)
void cast_bf16(const float* __restrict__ in, __nv_bfloat16* __restrict__ out, int n4)
{
    int i = blockIdx.x * blockDim.x + threadIdx.x;
    if (i >= n4) return;
    float4 v = *(const float4*)(in + (size_t)i * 4);
    __nv_bfloat162 lo = __floats2bfloat162_rn(v.x, v.y);
    __nv_bfloat162 hi = __floats2bfloat162_rn(v.z, v.w);
    *(__nv_bfloat162*)(out + (size_t)i * 4)     = lo;
    *(__nv_bfloat162*)(out + (size_t)i * 4 + 2) = hi;
}

// ---------------------------------------------------------------------------
// Transpose + cast: in[K,N] fp32 -> out[N,K] bf16   (K=N=1024)
// ---------------------------------------------------------------------------
__global__ __launch_bounds__(256)
void transpose_cast(const float* __restrict__ in, __nv_bfloat16* __restrict__ out)
{
    __shared__ float tile[32][33];
    const int n0 = blockIdx.x * 32;
    const int k0 = blockIdx.y * 32;
    const int tx = threadIdx.x;
    const int ty = threadIdx.y;  // 0..7
#pragma unroll
    for (int i = 0; i < 32; i += 8)
        tile[ty + i][tx] = in[(size_t)(k0 + ty + i) * DMODEL + n0 + tx];
    __syncthreads();
#pragma unroll
    for (int i = 0; i < 32; i += 8)
        out[(size_t)(n0 + ty + i) * DMODEL + k0 + tx] = __float2bfloat16(tile[tx][ty + i]);
}

// ---------------------------------------------------------------------------
// Flash attention (fp32, online softmax) — unchanged
// ---------------------------------------------------------------------------
#define AQ  64
#define AKV 32

__global__ __launch_bounds__(128)
void attn_kernel(const float* __restrict__ Q, const float* __restrict__ K,
                 const float* __restrict__ V, float* __restrict__ O)
{
    __shared__ float Qs[AQ][HDIM + 1];
    __shared__ float Ks[AKV][HDIM + 1];
    __shared__ float Vs[AKV][HDIM + 1];
    __shared__ float Ps[AQ][AKV + 1];
    __shared__ float m_s[AQ], l_s[AQ], al_s[AQ];

    const int t  = threadIdx.x;
    const int b  = blockIdx.z;
    const int h  = blockIdx.y;
    const int q0 = blockIdx.x * AQ;
    const size_t base = (size_t)b * SEQ * DMODEL + (size_t)h * HDIM;

    for (int i = t; i < AQ * (HDIM / 4); i += 128) {
        int r = i >> 4;
        int c = (i & 15) << 2;
        float4 qv = *(const float4*)(Q + base + (size_t)(q0 + r) * DMODEL + c);
        Qs[r][c] = qv.x; Qs[r][c+1] = qv.y; Qs[r][c+2] = qv.z; Qs[r][c+3] = qv.w;
    }
    if (t < AQ) { m_s[t] = -1e30f; l_s[t] = 0.f; }

    const int rg  = t & 15;
    const int grp = t >> 4;
    const int r0  = rg * 4;
    const int j0  = grp * 4;
    const int d0  = grp * 8;

    float o[4][8];
#pragma unroll
    for (int i = 0; i < 4; i++)
#pragma unroll
        for (int d = 0; d < 8; d++) o[i][d] = 0.f;

    __syncthreads();

    for (int kv0 = 0; kv0 < SEQ; kv0 += AKV) {
        for (int i = t; i < AKV * (HDIM / 4); i += 128) {
            int r = i >> 4;
            int c = (i & 15) << 2;
            float4 kv = *(const float4*)(K + base + (size_t)(kv0 + r) * DMODEL + c);
            Ks[r][c] = kv.x; Ks[r][c+1] = kv.y; Ks[r][c+2] = kv.z; Ks[r][c+3] = kv.w;
            float4 vv = *(const float4*)(V + base + (size_t)(kv0 + r) * DMODEL + c);
            Vs[r][c] = vv.x; Vs[r][c+1] = vv.y; Vs[r][c+2] = vv.z; Vs[r][c+3] = vv.w;
        }
        __syncthreads();

        float s[4][4];
#pragma unroll
        for (int i = 0; i < 4; i++)
#pragma unroll
            for (int j = 0; j < 4; j++) s[i][j] = 0.f;
#pragma unroll 8
        for (int d = 0; d < HDIM; d++) {
            float qv[4], kvv[4];
#pragma unroll
            for (int i = 0; i < 4; i++) qv[i] = Qs[r0 + i][d];
#pragma unroll
            for (int j = 0; j < 4; j++) kvv[j] = Ks[j0 + j][d];
#pragma unroll
            for (int i = 0; i < 4; i++)
#pragma unroll
                for (int j = 0; j < 4; j++)
                    s[i][j] = fmaf(qv[i], kvv[j], s[i][j]);
        }
#pragma unroll
        for (int i = 0; i < 4; i++)
#pragma unroll
            for (int j = 0; j < 4; j++)
                Ps[r0 + i][j0 + j] = s[i][j] * 0.125f;
        __syncthreads();

        if (t < AQ) {
            float mold = m_s[t];
            float mx = mold;
#pragma unroll
            for (int j = 0; j < AKV; j++) mx = fmaxf(mx, Ps[t][j]);
            float lsum = 0.f;
#pragma unroll
            for (int j = 0; j < AKV; j++) {
                float p = __expf(Ps[t][j] - mx);
                Ps[t][j] = p;
                lsum += p;
            }
            float alpha = __expf(mold - mx);
            m_s[t] = mx;
            l_s[t] = l_s[t] * alpha + lsum;
            al_s[t] = alpha;
        }
        __syncthreads();

        float al[4];
#pragma unroll
        for (int i = 0; i < 4; i++) al[i] = al_s[r0 + i];
#pragma unroll
        for (int i = 0; i < 4; i++)
#pragma unroll
            for (int d = 0; d < 8; d++) o[i][d] *= al[i];
#pragma unroll 4
        for (int j = 0; j < AKV; j++) {
            float p[4], vv[8];
#pragma unroll
            for (int i = 0; i < 4; i++) p[i] = Ps[r0 + i][j];
#pragma unroll
            for (int d = 0; d < 8; d++) vv[d] = Vs[j][d0 + d];
#pragma unroll
            for (int i = 0; i < 4; i++)
#pragma unroll
                for (int d = 0; d < 8; d++)
                    o[i][d] = fmaf(p[i], vv[d], o[i][d]);
        }
        __syncthreads();
    }

#pragma unroll
    for (int i = 0; i < 4; i++) {
        float inv = 1.f / l_s[r0 + i];
        float4 v0 = make_float4(o[i][0]*inv, o[i][1]*inv, o[i][2]*inv, o[i][3]*inv);
        float4 v1 = make_float4(o[i][4]*inv, o[i][5]*inv, o[i][6]*inv, o[i][7]*inv);
        float* op = O + base + (size_t)(q0 + r0 + i) * DMODEL + d0;
        *(float4*)op       = v0;
        *(float4*)(op + 4) = v1;
    }
}

// ---------------------------------------------------------------------------
// LayerNorm: one block per row (1024 elems), 256 threads, eps = 1e-6
// ---------------------------------------------------------------------------
__global__ __launch_bounds__(256)
void ln_kernel(const float* __restrict__ Y, const float* __restrict__ gamma,
               const float* __restrict__ beta, float* __restrict__ out)
{
    const int row = blockIdx.x;
    const int t = threadIdx.x;
    const float* y = Y + (size_t)row * DMODEL;

    float4 v = *(const float4*)(y + t * 4);
    float s  = v.x + v.y + v.z + v.w;
    float ss = v.x*v.x + v.y*v.y + v.z*v.z + v.w*v.w;

    __shared__ float rs[8], rss[8];
    int lane = t & 31, wid = t >> 5;
#pragma unroll
    for (int o = 16; o > 0; o >>= 1) {
        s  += __shfl_xor_sync(0xffffffffu, s,  o);
        ss += __shfl_xor_sync(0xffffffffu, ss, o);
    }
    if (lane == 0) { rs[wid] = s; rss[wid] = ss; }
    __syncthreads();
    if (wid == 0) {
        s  = (lane < 8) ? rs[lane]  : 0.f;
        ss = (lane < 8) ? rss[lane] : 0.f;
#pragma unroll
        for (int o = 4; o > 0; o >>= 1) {
            s  += __shfl_xor_sync(0xffffffffu, s,  o);
            ss += __shfl_xor_sync(0xffffffffu, ss, o);
        }
        if (lane == 0) { rs[0] = s; rss[0] = ss; }
    }
    __syncthreads();

    float mean = rs[0] * (1.f / DMODEL);
    float var  = rss[0] * (1.f / DMODEL) - mean * mean;
    float rstd = rsqrtf(var + 1e-6f);

    float4 g  = *(const float4*)(gamma + t * 4);
    float4 be = *(const float4*)(beta  + t * 4);
    float4 r;
    r.x = (v.x - mean) * rstd * g.x + be.x;
    r.y = (v.y - mean) * rstd * g.y + be.y;
    r.z = (v.z - mean) * rstd * g.z + be.z;
    r.w = (v.w - mean) * rstd * g.w + be.w;
    *(float4*)(out + (size_t)row * DMODEL + t * 4) = r;
}

// ---------------------------------------------------------------------------
// Launch
// ---------------------------------------------------------------------------
extern "C" void kernel_launch(void* const* d_in, const int* in_sizes, int n_in,
                              void* d_out, int out_size)
{
    const float* x      = (const float*)d_in[0];
    const float* w_q    = (const float*)d_in[1];
    const float* w_k    = (const float*)d_in[2];
    const float* w_v    = (const float*)d_in[3];
    const float* w_proj = (const float*)d_in[4];
    const float* b_proj = (const float*)d_in[5];
    const float* gamma  = (const float*)d_in[6];
    const float* beta   = (const float*)d_in[7];
    float* out = (float*)d_out;

    float *q, *k, *v, *o, *y;
    __nv_bfloat16 *xb, *ob, *wqb, *wkb, *wvb, *wpb;
    cudaGetSymbolAddress((void**)&q,  g_q);
    cudaGetSymbolAddress((void**)&k,  g_k);
    cudaGetSymbolAddress((void**)&v,  g_v);
    cudaGetSymbolAddress((void**)&o,  g_o);
    cudaGetSymbolAddress((void**)&y,  g_y);
    cudaGetSymbolAddress((void**)&xb, g_xb);
    cudaGetSymbolAddress((void**)&ob, g_ob);
    cudaGetSymbolAddress((void**)&wqb, g_wqb);
    cudaGetSymbolAddress((void**)&wkb, g_wkb);
    cudaGetSymbolAddress((void**)&wvb, g_wvb);
    cudaGetSymbolAddress((void**)&wpb, g_wpb);

    // Casts / weight transposes
    const int n4 = MROWS * DMODEL / 4;
    cast_bf16<<<(n4 + 255) / 256, 256>>>(x, xb, n4);
    dim3 tg(DMODEL / 32, DMODEL / 32), tb(32, 8);
    transpose_cast<<<tg, tb>>>(w_q, wqb);
    transpose_cast<<<tg, tb>>>(w_k, wkb);
    transpose_cast<<<tg, tb>>>(w_v, wvb);
    transpose_cast<<<tg, tb>>>(w_proj, wpb);

    // QKV projections on tensor cores (mma.sync bf16)
    dim3 gg(DMODEL / BN, MROWS / BM);   // (8, 64)
    gemm_mma<<<gg, 256>>>(xb, wqb, q, nullptr, nullptr);
    gemm_mma<<<gg, 256>>>(xb, wkb, k, nullptr, nullptr);
    gemm_mma<<<gg, 256>>>(xb, wvb, v, nullptr, nullptr);

    // Attention (fp32 SIMT this round)
    dim3 ga(SEQ / AQ, NHEAD, BATCH);      // (32, 16, 4)
    attn_kernel<<<ga, 128>>>(q, k, v, o);

    // proj + bias + residual on tensor cores
    cast_bf16<<<(n4 + 255) / 256, 256>>>(o, ob, n4);
    gemm_mma<<<gg, 256>>>(ob, wpb, y, b_proj, x);

    ln_kernel<<<MROWS, 256>>>(y, gamma, beta, out);
}

// round 5
// speedup vs baseline: 7.3190x; 4.3200x over previous
#include <cuda_runtime.h>
#include <cuda_bf16.h>
#include <cstdint>

// Problem dims (fixed)
#define BATCH  4
#define SEQ    2048
#define DMODEL 1024
#define NHEAD  16
#define HDIM   64
#define MROWS  (BATCH*SEQ)   // 8192

// ---------------------------------------------------------------------------
// Scratch (device-static: allocation-free per harness rules)
// ---------------------------------------------------------------------------
__device__ float g_y[(size_t)MROWS*DMODEL];
__device__ __nv_bfloat16 g_xb[(size_t)MROWS*DMODEL];
__device__ __nv_bfloat16 g_qb[(size_t)MROWS*DMODEL];
__device__ __nv_bfloat16 g_kb[(size_t)MROWS*DMODEL];
__device__ __nv_bfloat16 g_vb[(size_t)MROWS*DMODEL];
__device__ __nv_bfloat16 g_ob[(size_t)MROWS*DMODEL];
__device__ __nv_bfloat16 g_wqb[(size_t)DMODEL*DMODEL];
__device__ __nv_bfloat16 g_wkb[(size_t)DMODEL*DMODEL];
__device__ __nv_bfloat16 g_wvb[(size_t)DMODEL*DMODEL];
__device__ __nv_bfloat16 g_wpb[(size_t)DMODEL*DMODEL];

// ---------------------------------------------------------------------------
// PTX helpers (base ISA only — sm_103 target has no tcgen05)
// ---------------------------------------------------------------------------
__device__ __forceinline__ uint32_t smem_u32(const void* p) {
    uint32_t a;
    asm("{ .reg .u64 t; cvta.to.shared.u64 t, %1; cvt.u32.u64 %0, t; }" : "=r"(a) : "l"(p));
    return a;
}
#define CP_ASYNC16(dst, src) \
    asm volatile("cp.async.cg.shared.global [%0], [%1], 16;" :: "r"(dst), "l"(src))
#define CP_COMMIT()   asm volatile("cp.async.commit_group;")
#define CP_WAIT(N)    asm volatile("cp.async.wait_group %0;" :: "n"(N))

__device__ __forceinline__ void ldmx4(uint32_t addr, uint32_t& r0, uint32_t& r1,
                                      uint32_t& r2, uint32_t& r3) {
    asm volatile("ldmatrix.sync.aligned.m8n8.x4.shared.b16 {%0,%1,%2,%3}, [%4];"
                 : "=r"(r0), "=r"(r1), "=r"(r2), "=r"(r3) : "r"(addr));
}
__device__ __forceinline__ void ldmx4t(uint32_t addr, uint32_t& r0, uint32_t& r1,
                                       uint32_t& r2, uint32_t& r3) {
    asm volatile("ldmatrix.sync.aligned.m8n8.x4.trans.shared.b16 {%0,%1,%2,%3}, [%4];"
                 : "=r"(r0), "=r"(r1), "=r"(r2), "=r"(r3) : "r"(addr));
}
__device__ __forceinline__ void mma_bf16(float c[4], uint32_t a0, uint32_t a1,
                                         uint32_t a2, uint32_t a3,
                                         uint32_t b0, uint32_t b1) {
    asm volatile("mma.sync.aligned.m16n8k16.row.col.f32.bf16.bf16.f32 "
                 "{%0,%1,%2,%3}, {%4,%5,%6,%7}, {%8,%9}, {%0,%1,%2,%3};"
                 : "+f"(c[0]), "+f"(c[1]), "+f"(c[2]), "+f"(c[3])
                 : "r"(a0), "r"(a1), "r"(a2), "r"(a3), "r"(b0), "r"(b1));
}
__device__ __forceinline__ float ex2(float x) {
    float y; asm("ex2.approx.ftz.f32 %0, %1;" : "=f"(y) : "f"(x)); return y;
}
__device__ __forceinline__ uint32_t pack_bf16(float a, float b) {
    __nv_bfloat162 v = __floats2bfloat162_rn(a, b);
    return *(uint32_t*)&v;
}

// ---------------------------------------------------------------------------
// bf16 mma.sync GEMM: C[M,N] = A[M,K] @ Bt[N,K]^T
// 128x128 tile, BK=32, 256 threads (2x4 warps, 64x32 warp tile), cp.async
// double-buffered. OT=float: fp32 out + optional bias/resid. OT=bf16: bf16 out.
// ---------------------------------------------------------------------------
#define BM  128
#define BN  128
#define BKK 32
#define STR 40
#define NITER (DMODEL / BKK)

template<typename OT>
__global__ __launch_bounds__(256)
void gemm_mma(const __nv_bfloat16* __restrict__ A, const __nv_bfloat16* __restrict__ Bt,
              OT* __restrict__ C, const float* __restrict__ bias,
              const float* __restrict__ resid)
{
    __shared__ __nv_bfloat16 As[2][BM * STR];
    __shared__ __nv_bfloat16 Bs[2][BM * STR];

    const int t    = threadIdx.x;
    const int lane = t & 31;
    const int warp = t >> 5;
    const int wm   = (warp >> 2) * 64;
    const int wn   = (warp & 3) * 32;
    const int bm   = blockIdx.y * BM;
    const int bn   = blockIdx.x * BN;

    const int lr = t >> 2;
    const int lc = (t & 3) * 8;

    const __nv_bfloat16* a0 = A  + (size_t)(bm + lr) * DMODEL + lc;
    const __nv_bfloat16* a1 = A  + (size_t)(bm + lr + 64) * DMODEL + lc;
    const __nv_bfloat16* b0 = Bt + (size_t)(bn + lr) * DMODEL + lc;
    const __nv_bfloat16* b1 = Bt + (size_t)(bn + lr + 64) * DMODEL + lc;

    const uint32_t sA = smem_u32(As);
    const uint32_t sB = smem_u32(Bs);
    const uint32_t dA0 = sA + (uint32_t)(lr * STR + lc) * 2;
    const uint32_t dA1 = sA + (uint32_t)((lr + 64) * STR + lc) * 2;
    const uint32_t dB0 = sB + (uint32_t)(lr * STR + lc) * 2;
    const uint32_t dB1 = sB + (uint32_t)((lr + 64) * STR + lc) * 2;
    const uint32_t sbuf = BM * STR * 2;

    float acc[4][4][4];
#pragma unroll
    for (int i = 0; i < 4; i++)
#pragma unroll
        for (int j = 0; j < 4; j++)
#pragma unroll
            for (int e = 0; e < 4; e++) acc[i][j][e] = 0.f;

    CP_ASYNC16(dA0, a0); CP_ASYNC16(dA1, a1);
    CP_ASYNC16(dB0, b0); CP_ASYNC16(dB1, b1);
    CP_COMMIT();

    const uint32_t aoff = (uint32_t)((wm + (lane & 15)) * STR + ((lane >> 4) << 3)) * 2;
    const uint32_t boff = (uint32_t)((wn + ((lane >> 4) << 3) + (lane & 7)) * STR
                                     + (((lane >> 3) & 1) << 3)) * 2;

    for (int it = 0; it < NITER; it++) {
        const int s = it & 1;
        if (it + 1 < NITER) {
            const int koff = (it + 1) * BKK;
            const uint32_t bo = (uint32_t)((it + 1) & 1) * sbuf;
            CP_ASYNC16(dA0 + bo, a0 + koff); CP_ASYNC16(dA1 + bo, a1 + koff);
            CP_ASYNC16(dB0 + bo, b0 + koff); CP_ASYNC16(dB1 + bo, b1 + koff);
            CP_COMMIT();
            CP_WAIT(1);
        } else {
            CP_WAIT(0);
        }
        __syncthreads();

        const uint32_t base = (uint32_t)s * sbuf;
#pragma unroll
        for (int kh = 0; kh < 2; kh++) {
            uint32_t a[4][4], bfr[4][2];
#pragma unroll
            for (int mi = 0; mi < 4; mi++) {
                uint32_t addr = sA + base + aoff + (uint32_t)(mi * 16 * STR + kh * 16) * 2;
                ldmx4(addr, a[mi][0], a[mi][1], a[mi][2], a[mi][3]);
            }
#pragma unroll
            for (int j = 0; j < 2; j++) {
                uint32_t addr = sB + base + boff + (uint32_t)(j * 16 * STR + kh * 16) * 2;
                uint32_t r0, r1, r2, r3;
                ldmx4(addr, r0, r1, r2, r3);
                bfr[j*2][0] = r0; bfr[j*2][1] = r1;
                bfr[j*2+1][0] = r2; bfr[j*2+1][1] = r3;
            }
#pragma unroll
            for (int mi = 0; mi < 4; mi++)
#pragma unroll
                for (int ni = 0; ni < 4; ni++)
                    mma_bf16(acc[mi][ni], a[mi][0], a[mi][1], a[mi][2], a[mi][3],
                             bfr[ni][0], bfr[ni][1]);
        }
        __syncthreads();
    }

    const int r0 = bm + wm + (lane >> 2);
    const int c0 = bn + wn + (lane & 3) * 2;
#pragma unroll
    for (int mi = 0; mi < 4; mi++) {
#pragma unroll
        for (int ni = 0; ni < 4; ni++) {
            const int row = r0 + mi * 16;
            const int col = c0 + ni * 8;
            if constexpr (sizeof(OT) == 4) {
                float2 v0 = make_float2(acc[mi][ni][0], acc[mi][ni][1]);
                float2 v1 = make_float2(acc[mi][ni][2], acc[mi][ni][3]);
                if (bias) {
                    const float2 bb = *(const float2*)(bias + col);
                    v0.x += bb.x; v0.y += bb.y; v1.x += bb.x; v1.y += bb.y;
                }
                if (resid) {
                    const float2 x0 = *(const float2*)(resid + (size_t)row * DMODEL + col);
                    const float2 x1 = *(const float2*)(resid + (size_t)(row + 8) * DMODEL + col);
                    v0.x += x0.x; v0.y += x0.y; v1.x += x1.x; v1.y += x1.y;
                }
                *(float2*)((float*)C + (size_t)row * DMODEL + col)       = v0;
                *(float2*)((float*)C + (size_t)(row + 8) * DMODEL + col) = v1;
            } else {
                *(__nv_bfloat162*)((__nv_bfloat16*)C + (size_t)row * DMODEL + col) =
                    __floats2bfloat162_rn(acc[mi][ni][0], acc[mi][ni][1]);
                *(__nv_bfloat162*)((__nv_bfloat16*)C + (size_t)(row + 8) * DMODEL + col) =
                    __floats2bfloat162_rn(acc[mi][ni][2], acc[mi][ni][3]);
            }
        }
    }
}

// ---------------------------------------------------------------------------
// Flash attention on mma.sync (bf16 in/out, fp32 softmax+accum).
// 256 threads, 8 warps; warp w owns Q rows [16w, 16w+16). BQ=128, BKV=64.
// ---------------------------------------------------------------------------
#define ATQ   128
#define ATKV  64
#define ASTR  72
#define AQBYTES  (ATQ * ASTR * 2)        // 18432
#define AKVBYTES (ATKV * ASTR * 2)       // 9216
#define ASMEM    (AQBYTES + 4 * AKVBYTES) // 55296
#define CEXP  0.180336880f               // 0.125 * log2(e)
#define NKV   (SEQ / ATKV)               // 32

__global__ __launch_bounds__(256)
void attn_mma(const __nv_bfloat16* __restrict__ Q, const __nv_bfloat16* __restrict__ K,
              const __nv_bfloat16* __restrict__ V, __nv_bfloat16* __restrict__ O)
{
    extern __shared__ char smattn[];
    const uint32_t sQ = smem_u32(smattn);
    const uint32_t sK = sQ + AQBYTES;
    const uint32_t sV = sK + 2 * AKVBYTES;

    const int t = threadIdx.x, lane = t & 31, warp = t >> 5;
    const int b = blockIdx.z, h = blockIdx.y;
    const int q0 = blockIdx.x * ATQ;
    const size_t base = (size_t)b * SEQ * DMODEL + (size_t)h * HDIM;

    // prologue: Q tile (1024 x 16B) + KV buf 0 (512 x 16B each tensor)
#pragma unroll
    for (int i = 0; i < 4; i++) {
        int idx = t + i * 256, row = idx >> 3, ch = idx & 7;
        CP_ASYNC16(sQ + (uint32_t)(row * ASTR + ch * 8) * 2,
                   Q + base + (size_t)(q0 + row) * DMODEL + ch * 8);
    }
#pragma unroll
    for (int i = 0; i < 2; i++) {
        int idx = t + i * 256, row = idx >> 3, ch = idx & 7;
        CP_ASYNC16(sK + (uint32_t)(row * ASTR + ch * 8) * 2,
                   K + base + (size_t)row * DMODEL + ch * 8);
        CP_ASYNC16(sV + (uint32_t)(row * ASTR + ch * 8) * 2,
                   V + base + (size_t)row * DMODEL + ch * 8);
    }
    CP_COMMIT();
    CP_WAIT(0);
    __syncthreads();

    // Q fragments, resident for the whole KV loop
    uint32_t qa[4][4];
    {
        const uint32_t aq = (uint32_t)((warp * 16 + (lane & 15)) * ASTR + ((lane >> 4) << 3));
#pragma unroll
        for (int kh = 0; kh < 4; kh++)
            ldmx4(sQ + (aq + kh * 16) * 2, qa[kh][0], qa[kh][1], qa[kh][2], qa[kh][3]);
    }

    float oacc[8][4];
#pragma unroll
    for (int j = 0; j < 8; j++)
#pragma unroll
        for (int e = 0; e < 4; e++) oacc[j][e] = 0.f;
    float m0 = -1e30f, m1 = -1e30f, l0 = 0.f, l1 = 0.f;

    const uint32_t koff = (uint32_t)((((lane >> 4) << 3) + (lane & 7)) * ASTR
                                     + (((lane >> 3) & 1) << 3));
    const uint32_t voff = (uint32_t)((lane & 15) * ASTR + ((lane >> 4) << 3));

    for (int it = 0; it < NKV; it++) {
        const int s = it & 1;
        __syncthreads();   // all warps done reading buf s^1 before overwrite
        if (it + 1 < NKV) {
            const uint32_t bo = (uint32_t)((it + 1) & 1) * AKVBYTES;
            const size_t kvb = base + (size_t)((it + 1) * ATKV) * DMODEL;
#pragma unroll
            for (int i = 0; i < 2; i++) {
                int idx = t + i * 256, row = idx >> 3, ch = idx & 7;
                CP_ASYNC16(sK + bo + (uint32_t)(row * ASTR + ch * 8) * 2,
                           K + kvb + (size_t)row * DMODEL + ch * 8);
                CP_ASYNC16(sV + bo + (uint32_t)(row * ASTR + ch * 8) * 2,
                           V + kvb + (size_t)row * DMODEL + ch * 8);
            }
            CP_COMMIT();
            CP_WAIT(1);
        } else {
            CP_WAIT(0);
        }
        __syncthreads();

        // S = Q @ K^T  (warp: 16 x 64)
        float sacc[8][4];
#pragma unroll
        for (int j = 0; j < 8; j++)
#pragma unroll
            for (int e = 0; e < 4; e++) sacc[j][e] = 0.f;
        const uint32_t kb = sK + (uint32_t)s * AKVBYTES;
#pragma unroll
        for (int kh = 0; kh < 4; kh++) {
#pragma unroll
            for (int j2 = 0; j2 < 4; j2++) {
                uint32_t r0, r1, r2, r3;
                ldmx4(kb + (koff + (uint32_t)(j2 * 16 * ASTR + kh * 16)) * 2, r0, r1, r2, r3);
                mma_bf16(sacc[j2*2],   qa[kh][0], qa[kh][1], qa[kh][2], qa[kh][3], r0, r1);
                mma_bf16(sacc[j2*2+1], qa[kh][0], qa[kh][1], qa[kh][2], qa[kh][3], r2, r3);
            }
        }

        // online softmax (fp32); rows r = 16*warp + lane>>2 and r+8
        float mx0 = m0, mx1 = m1;
#pragma unroll
        for (int j = 0; j < 8; j++) {
            mx0 = fmaxf(mx0, fmaxf(sacc[j][0], sacc[j][1]));
            mx1 = fmaxf(mx1, fmaxf(sacc[j][2], sacc[j][3]));
        }
        mx0 = fmaxf(mx0, __shfl_xor_sync(0xffffffffu, mx0, 1));
        mx0 = fmaxf(mx0, __shfl_xor_sync(0xffffffffu, mx0, 2));
        mx1 = fmaxf(mx1, __shfl_xor_sync(0xffffffffu, mx1, 1));
        mx1 = fmaxf(mx1, __shfl_xor_sync(0xffffffffu, mx1, 2));
        const float al0 = ex2((m0 - mx0) * CEXP);
        const float al1 = ex2((m1 - mx1) * CEXP);
        m0 = mx0; m1 = mx1;

        uint32_t pa[4][4];
        float rs0 = 0.f, rs1 = 0.f;
#pragma unroll
        for (int kk = 0; kk < 4; kk++) {
#pragma unroll
            for (int u = 0; u < 2; u++) {
                const int j = kk * 2 + u;
                float p0 = ex2((sacc[j][0] - mx0) * CEXP);
                float p1 = ex2((sacc[j][1] - mx0) * CEXP);
                float p2 = ex2((sacc[j][2] - mx1) * CEXP);
                float p3 = ex2((sacc[j][3] - mx1) * CEXP);
                rs0 += p0 + p1; rs1 += p2 + p3;
                pa[kk][u*2]     = pack_bf16(p0, p1);   // a0/a2: row r
                pa[kk][u*2 + 1] = pack_bf16(p2, p3);   // a1/a3: row r+8
            }
        }
        l0 = l0 * al0 + rs0;
        l1 = l1 * al1 + rs1;
#pragma unroll
        for (int j = 0; j < 8; j++) {
            oacc[j][0] *= al0; oacc[j][1] *= al0;
            oacc[j][2] *= al1; oacc[j][3] *= al1;
        }

        // O += P @ V
        const uint32_t vb = sV + (uint32_t)s * AKVBYTES;
#pragma unroll
        for (int kk = 0; kk < 4; kk++) {
#pragma unroll
            for (int j2 = 0; j2 < 4; j2++) {
                uint32_t r0, r1, r2, r3;
                ldmx4t(vb + (voff + (uint32_t)(kk * 16 * ASTR + j2 * 16)) * 2, r0, r1, r2, r3);
                mma_bf16(oacc[j2*2],   pa[kk][0], pa[kk][1], pa[kk][2], pa[kk][3], r0, r1);
                mma_bf16(oacc[j2*2+1], pa[kk][0], pa[kk][1], pa[kk][2], pa[kk][3], r2, r3);
            }
        }
    }

    l0 += __shfl_xor_sync(0xffffffffu, l0, 1);
    l0 += __shfl_xor_sync(0xffffffffu, l0, 2);
    l1 += __shfl_xor_sync(0xffffffffu, l1, 1);
    l1 += __shfl_xor_sync(0xffffffffu, l1, 2);
    const float inv0 = 1.f / l0, inv1 = 1.f / l1;

    const int r = warp * 16 + (lane >> 2);
    __nv_bfloat16* o0 = O + (size_t)(b * SEQ + q0 + r) * DMODEL + h * HDIM + (lane & 3) * 2;
    __nv_bfloat16* o1 = o0 + (size_t)8 * DMODEL;
#pragma unroll
    for (int jn = 0; jn < 8; jn++) {
        *(__nv_bfloat162*)(o0 + jn * 8) =
            __floats2bfloat162_rn(oacc[jn][0] * inv0, oacc[jn][1] * inv0);
        *(__nv_bfloat162*)(o1 + jn * 8) =
            __floats2bfloat162_rn(oacc[jn][2] * inv1, oacc[jn][3] * inv1);
    }
}

// ---------------------------------------------------------------------------
// fp32 -> bf16 cast (elementwise, vectorized)
// ---------------------------------------------------------------------------
__global__ __launch_bounds__(256)
void cast_bf16(const float* __restrict__ in, __nv_bfloat16* __restrict__ out, int n4)
{
    int i = blockIdx.x * blockDim.x + threadIdx.x;
    if (i >= n4) return;
    float4 v = *(const float4*)(in + (size_t)i * 4);
    *(__nv_bfloat162*)(out + (size_t)i * 4)     = __floats2bfloat162_rn(v.x, v.y);
    *(__nv_bfloat162*)(out + (size_t)i * 4 + 2) = __floats2bfloat162_rn(v.z, v.w);
}

// ---------------------------------------------------------------------------
// Transpose + cast all 4 weights: in[K,N] fp32 -> out[N,K] bf16 (z selects)
// ---------------------------------------------------------------------------
__global__ __launch_bounds__(256)
void transpose_cast4(const float* __restrict__ w0, const float* __restrict__ w1,
                     const float* __restrict__ w2, const float* __restrict__ w3,
                     __nv_bfloat16* __restrict__ o0, __nv_bfloat16* __restrict__ o1,
                     __nv_bfloat16* __restrict__ o2, __nv_bfloat16* __restrict__ o3)
{
    const float* in  = (blockIdx.z == 0) ? w0 : (blockIdx.z == 1) ? w1
                     : (blockIdx.z == 2) ? w2 : w3;
    __nv_bfloat16* out = (blockIdx.z == 0) ? o0 : (blockIdx.z == 1) ? o1
                       : (blockIdx.z == 2) ? o2 : o3;
    __shared__ float tile[32][33];
    const int n0 = blockIdx.x * 32;
    const int k0 = blockIdx.y * 32;
    const int tx = threadIdx.x & 31;
    const int ty = threadIdx.x >> 5;   // 0..7
#pragma unroll
    for (int i = 0; i < 32; i += 8)
        tile[ty + i][tx] = in[(size_t)(k0 + ty + i) * DMODEL + n0 + tx];
    __syncthreads();
#pragma unroll
    for (int i = 0; i < 32; i += 8)
        out[(size_t)(n0 + ty + i) * DMODEL + k0 + tx] = __float2bfloat16(tile[tx][ty + i]);
}

// ---------------------------------------------------------------------------
// LayerNorm: one block per row (1024 elems), 256 threads, eps = 1e-6
// ---------------------------------------------------------------------------
__global__ __launch_bounds__(256)
void ln_kernel(const float* __restrict__ Y, const float* __restrict__ gamma,
               const float* __restrict__ beta, float* __restrict__ out)
{
    const int row = blockIdx.x;
    const int t = threadIdx.x;
    const float* y = Y + (size_t)row * DMODEL;

    float4 v = *(const float4*)(y + t * 4);
    float s  = v.x + v.y + v.z + v.w;
    float ss = v.x*v.x + v.y*v.y + v.z*v.z + v.w*v.w;

    __shared__ float rs[8], rss[8];
    int lane = t & 31, wid = t >> 5;
#pragma unroll
    for (int o = 16; o > 0; o >>= 1) {
        s  += __shfl_xor_sync(0xffffffffu, s,  o);
        ss += __shfl_xor_sync(0xffffffffu, ss, o);
    }
    if (lane == 0) { rs[wid] = s; rss[wid] = ss; }
    __syncthreads();
    if (wid == 0) {
        s  = (lane < 8) ? rs[lane]  : 0.f;
        ss = (lane < 8) ? rss[lane] : 0.f;
#pragma unroll
        for (int o = 4; o > 0; o >>= 1) {
            s  += __shfl_xor_sync(0xffffffffu, s,  o);
            ss += __shfl_xor_sync(0xffffffffu, ss, o);
        }
        if (lane == 0) { rs[0] = s; rss[0] = ss; }
    }
    __syncthreads();

    float mean = rs[0] * (1.f / DMODEL);
    float var  = rss[0] * (1.f / DMODEL) - mean * mean;
    float rstd = rsqrtf(var + 1e-6f);

    float4 g  = *(const float4*)(gamma + t * 4);
    float4 be = *(const float4*)(beta  + t * 4);
    float4 r;
    r.x = (v.x - mean) * rstd * g.x + be.x;
    r.y = (v.y - mean) * rstd * g.y + be.y;
    r.z = (v.z - mean) * rstd * g.z + be.z;
    r.w = (v.w - mean) * rstd * g.w + be.w;
    *(float4*)(out + (size_t)row * DMODEL + t * 4) = r;
}

// ---------------------------------------------------------------------------
// Launch
// ---------------------------------------------------------------------------
extern "C" void kernel_launch(void* const* d_in, const int* in_sizes, int n_in,
                              void* d_out, int out_size)
{
    const float* x      = (const float*)d_in[0];
    const float* w_q    = (const float*)d_in[1];
    const float* w_k    = (const float*)d_in[2];
    const float* w_v    = (const float*)d_in[3];
    const float* w_proj = (const float*)d_in[4];
    const float* b_proj = (const float*)d_in[5];
    const float* gamma  = (const float*)d_in[6];
    const float* beta   = (const float*)d_in[7];
    float* out = (float*)d_out;

    float* y;
    __nv_bfloat16 *xb, *qb, *kb, *vb, *ob, *wqb, *wkb, *wvb, *wpb;
    cudaGetSymbolAddress((void**)&y,   g_y);
    cudaGetSymbolAddress((void**)&xb,  g_xb);
    cudaGetSymbolAddress((void**)&qb,  g_qb);
    cudaGetSymbolAddress((void**)&kb,  g_kb);
    cudaGetSymbolAddress((void**)&vb,  g_vb);
    cudaGetSymbolAddress((void**)&ob,  g_ob);
    cudaGetSymbolAddress((void**)&wqb, g_wqb);
    cudaGetSymbolAddress((void**)&wkb, g_wkb);
    cudaGetSymbolAddress((void**)&wvb, g_wvb);
    cudaGetSymbolAddress((void**)&wpb, g_wpb);

    cudaFuncSetAttribute(attn_mma, cudaFuncAttributeMaxDynamicSharedMemorySize, ASMEM);

    // Casts / weight transposes
    const int n4 = MROWS * DMODEL / 4;
    cast_bf16<<<(n4 + 255) / 256, 256>>>(x, xb, n4);
    dim3 tg(DMODEL / 32, DMODEL / 32, 4);
    transpose_cast4<<<tg, 256>>>(w_q, w_k, w_v, w_proj, wqb, wkb, wvb, wpb);

    // QKV projections (bf16 out)
    dim3 gg(DMODEL / BN, MROWS / BM);   // (8, 64)
    gemm_mma<__nv_bfloat16><<<gg, 256>>>(xb, wqb, qb, nullptr, nullptr);
    gemm_mma<__nv_bfloat16><<<gg, 256>>>(xb, wkb, kb, nullptr, nullptr);
    gemm_mma<__nv_bfloat16><<<gg, 256>>>(xb, wvb, vb, nullptr, nullptr);

    // Flash attention on tensor cores
    dim3 ga(SEQ / ATQ, NHEAD, BATCH);   // (16, 16, 4)
    attn_mma<<<ga, 256, ASMEM>>>(qb, kb, vb, ob);

    // proj + bias + residual (fp32 out)
    gemm_mma<float><<<gg, 256>>>(ob, wpb, y, b_proj, x);

    ln_kernel<<<MROWS, 256>>>(y, gamma, beta, out);
}

// round 7
// speedup vs baseline: 7.6466x; 1.0448x over previous
#include <cuda_runtime.h>
#include <cuda_bf16.h>
#include <cstdint>

// Problem dims (fixed)
#define BATCH  4
#define SEQ    2048
#define DMODEL 1024
#define NHEAD  16
#define HDIM   64
#define MROWS  (BATCH*SEQ)   // 8192

// ---------------------------------------------------------------------------
// Scratch (device-static: allocation-free per harness rules)
// ---------------------------------------------------------------------------
__device__ float g_y[(size_t)MROWS*DMODEL];
__device__ __nv_bfloat16 g_xb[(size_t)MROWS*DMODEL];
__device__ __nv_bfloat16 g_qkvb[(size_t)3*MROWS*DMODEL];
__device__ __nv_bfloat16 g_ob[(size_t)MROWS*DMODEL];
__device__ __nv_bfloat16 g_wqkv[(size_t)3*DMODEL*DMODEL];  // [3*N, K] transposed
__device__ __nv_bfloat16 g_wpb[(size_t)DMODEL*DMODEL];

// ---------------------------------------------------------------------------
// PTX helpers (base ISA only — sm_103 target has no tcgen05)
// ---------------------------------------------------------------------------
__device__ __forceinline__ uint32_t smem_u32(const void* p) {
    uint32_t a;
    asm("{ .reg .u64 t; cvta.to.shared.u64 t, %1; cvt.u32.u64 %0, t; }" : "=r"(a) : "l"(p));
    return a;
}
#define CP_ASYNC16(dst, src) \
    asm volatile("cp.async.cg.shared.global [%0], [%1], 16;" :: "r"(dst), "l"(src))
#define CP_COMMIT()   asm volatile("cp.async.commit_group;")
#define CP_WAIT(N)    asm volatile("cp.async.wait_group %0;" :: "n"(N))

__device__ __forceinline__ void ldmx4(uint32_t addr, uint32_t& r0, uint32_t& r1,
                                      uint32_t& r2, uint32_t& r3) {
    asm volatile("ldmatrix.sync.aligned.m8n8.x4.shared.b16 {%0,%1,%2,%3}, [%4];"
                 : "=r"(r0), "=r"(r1), "=r"(r2), "=r"(r3) : "r"(addr));
}
__device__ __forceinline__ void ldmx4t(uint32_t addr, uint32_t& r0, uint32_t& r1,
                                       uint32_t& r2, uint32_t& r3) {
    asm volatile("ldmatrix.sync.aligned.m8n8.x4.trans.shared.b16 {%0,%1,%2,%3}, [%4];"
                 : "=r"(r0), "=r"(r1), "=r"(r2), "=r"(r3) : "r"(addr));
}
__device__ __forceinline__ void mma_bf16(float c[4], uint32_t a0, uint32_t a1,
                                         uint32_t a2, uint32_t a3,
                                         uint32_t b0, uint32_t b1) {
    asm volatile("mma.sync.aligned.m16n8k16.row.col.f32.bf16.bf16.f32 "
                 "{%0,%1,%2,%3}, {%4,%5,%6,%7}, {%8,%9}, {%0,%1,%2,%3};"
                 : "+f"(c[0]), "+f"(c[1]), "+f"(c[2]), "+f"(c[3])
                 : "r"(a0), "r"(a1), "r"(a2), "r"(a3), "r"(b0), "r"(b1));
}
__device__ __forceinline__ float ex2(float x) {
    float y; asm("ex2.approx.ftz.f32 %0, %1;" : "=f"(y) : "f"(x)); return y;
}
__device__ __forceinline__ uint32_t pack_bf16(float a, float b) {
    __nv_bfloat162 v = __floats2bfloat162_rn(a, b);
    return *(uint32_t*)&v;
}

// ---------------------------------------------------------------------------
// bf16 mma.sync GEMM: C = A[M,K] @ Bt[N,K]^T, 128x128 tile, BK=32,
// 3-stage cp.async ring, ONE __syncthreads per K-iteration.
// MODE 0: bf16 out, N=3072 fused QKV (output split into 3 [MROWS,DMODEL]).
// MODE 1: fp32 out + bias + resid, N=1024.
// ---------------------------------------------------------------------------
#define BM  128
#define BN  128
#define BKK 32
#define STR 40
#define NITER (DMODEL / BKK)          // 32
#define STGB  (BM * STR * 2)          // 10240 B per operand per stage
#define GSTG  (2 * STGB)              // 20480 B per stage (A + B)
#define GSMEM (3 * GSTG)              // 61440 B

template<int MODE>
__global__ __launch_bounds__(256)
void gemm_mma(const __nv_bfloat16* __restrict__ A, const __nv_bfloat16* __restrict__ Bt,
              void* __restrict__ Cv, const float* __restrict__ bias,
              const float* __restrict__ resid)
{
    extern __shared__ char gsm[];
    const uint32_t sS = smem_u32(gsm);

    const int t    = threadIdx.x;
    const int lane = t & 31;
    const int warp = t >> 5;
    const int wm   = (warp >> 2) * 64;
    const int wn   = (warp & 3) * 32;
    const int bm   = blockIdx.y * BM;
    const int bn   = blockIdx.x * BN;

    const int lr = t >> 2;
    const int lc = (t & 3) * 8;

    const __nv_bfloat16* a0 = A  + (size_t)(bm + lr) * DMODEL + lc;
    const __nv_bfloat16* a1 = A  + (size_t)(bm + lr + 64) * DMODEL + lc;
    const __nv_bfloat16* b0 = Bt + (size_t)(bn + lr) * DMODEL + lc;
    const __nv_bfloat16* b1 = Bt + (size_t)(bn + lr + 64) * DMODEL + lc;

    const uint32_t dA0 = (uint32_t)(lr * STR + lc) * 2;
    const uint32_t dA1 = (uint32_t)((lr + 64) * STR + lc) * 2;

    float acc[4][4][4];
#pragma unroll
    for (int i = 0; i < 4; i++)
#pragma unroll
        for (int j = 0; j < 4; j++)
#pragma unroll
            for (int e = 0; e < 4; e++) acc[i][j][e] = 0.f;

    // prologue: stages 0,1
#pragma unroll
    for (int p = 0; p < 2; p++) {
        const uint32_t bo = sS + (uint32_t)p * GSTG;
        const int ko = p * BKK;
        CP_ASYNC16(bo + dA0, a0 + ko);
        CP_ASYNC16(bo + dA1, a1 + ko);
        CP_ASYNC16(bo + STGB + dA0, b0 + ko);
        CP_ASYNC16(bo + STGB + dA1, b1 + ko);
        CP_COMMIT();
    }

    const uint32_t aoff = (uint32_t)((wm + (lane & 15)) * STR + ((lane >> 4) << 3)) * 2;
    const uint32_t boff = STGB + (uint32_t)((wn + ((lane >> 4) << 3) + (lane & 7)) * STR
                                            + (((lane >> 3) & 1) << 3)) * 2;

    int buf = 0, nbuf = 2;
    for (int it = 0; it < NITER; it++) {
        if (it + 1 < NITER) { CP_WAIT(1); } else { CP_WAIT(0); }
        __syncthreads();
        if (it + 2 < NITER) {
            const uint32_t bo = sS + (uint32_t)nbuf * GSTG;
            const int ko = (it + 2) * BKK;
            CP_ASYNC16(bo + dA0, a0 + ko);
            CP_ASYNC16(bo + dA1, a1 + ko);
            CP_ASYNC16(bo + STGB + dA0, b0 + ko);
            CP_ASYNC16(bo + STGB + dA1, b1 + ko);
            CP_COMMIT();
            nbuf = (nbuf == 2) ? 0 : nbuf + 1;
        }

        const uint32_t base = sS + (uint32_t)buf * GSTG;
        buf = (buf == 2) ? 0 : buf + 1;
#pragma unroll
        for (int kh = 0; kh < 2; kh++) {
            uint32_t a[4][4], bfr[4][2];
#pragma unroll
            for (int mi = 0; mi < 4; mi++) {
                uint32_t addr = base + aoff + (uint32_t)(mi * 16 * STR + kh * 16) * 2;
                ldmx4(addr, a[mi][0], a[mi][1], a[mi][2], a[mi][3]);
            }
#pragma unroll
            for (int j = 0; j < 2; j++) {
                uint32_t addr = base + boff + (uint32_t)(j * 16 * STR + kh * 16) * 2;
                uint32_t r0, r1, r2, r3;
                ldmx4(addr, r0, r1, r2, r3);
                bfr[j*2][0] = r0; bfr[j*2][1] = r1;
                bfr[j*2+1][0] = r2; bfr[j*2+1][1] = r3;
            }
#pragma unroll
            for (int mi = 0; mi < 4; mi++)
#pragma unroll
                for (int ni = 0; ni < 4; ni++)
                    mma_bf16(acc[mi][ni], a[mi][0], a[mi][1], a[mi][2], a[mi][3],
                             bfr[ni][0], bfr[ni][1]);
        }
    }

    // epilogue
    const int r0 = bm + wm + (lane >> 2);
#pragma unroll
    for (int mi = 0; mi < 4; mi++) {
#pragma unroll
        for (int ni = 0; ni < 4; ni++) {
            const int row = r0 + mi * 16;
            if constexpr (MODE == 0) {
                __nv_bfloat16* Cb = (__nv_bfloat16*)Cv
                    + (size_t)(bn >> 10) * MROWS * DMODEL;
                const int col = (bn & 1023) + wn + (lane & 3) * 2 + ni * 8;
                *(__nv_bfloat162*)(Cb + (size_t)row * DMODEL + col) =
                    __floats2bfloat162_rn(acc[mi][ni][0], acc[mi][ni][1]);
                *(__nv_bfloat162*)(Cb + (size_t)(row + 8) * DMODEL + col) =
                    __floats2bfloat162_rn(acc[mi][ni][2], acc[mi][ni][3]);
            } else {
                float* Cf = (float*)Cv;
                const int col = bn + wn + (lane & 3) * 2 + ni * 8;
                float2 v0 = make_float2(acc[mi][ni][0], acc[mi][ni][1]);
                float2 v1 = make_float2(acc[mi][ni][2], acc[mi][ni][3]);
                const float2 bb = *(const float2*)(bias + col);
                const float2 x0 = *(const float2*)(resid + (size_t)row * DMODEL + col);
                const float2 x1 = *(const float2*)(resid + (size_t)(row + 8) * DMODEL + col);
                v0.x += bb.x + x0.x; v0.y += bb.y + x0.y;
                v1.x += bb.x + x1.x; v1.y += bb.y + x1.y;
                *(float2*)(Cf + (size_t)row * DMODEL + col)       = v0;
                *(float2*)(Cf + (size_t)(row + 8) * DMODEL + col) = v1;
            }
        }
    }
}

// ---------------------------------------------------------------------------
// Flash attention on mma.sync (bf16 in/out, fp32 softmax+accum).
// 256 threads, 8 warps, warp owns 16 Q rows. BQ=128, BKV=64.
// 3-stage KV ring, one __syncthreads per KV iteration.
// ---------------------------------------------------------------------------
#define ATQ   128
#define ATKV  64
#define ASTR  72
#define AQBYTES  (ATQ * ASTR * 2)          // 18432
#define AKVB     (ATKV * ASTR * 2)         // 9216 (per tensor)
#define ASTGB    (2 * AKVB)                // 18432 (K + V per stage)
#define ASMEM    (AQBYTES + 3 * ASTGB)     // 73728
#define CEXP  0.180336880f                 // 0.125 * log2(e)
#define NKV   (SEQ / ATKV)                 // 32

__global__ __launch_bounds__(256)
void attn_mma(const __nv_bfloat16* __restrict__ Q, const __nv_bfloat16* __restrict__ K,
              const __nv_bfloat16* __restrict__ V, __nv_bfloat16* __restrict__ O)
{
    extern __shared__ char smattn[];
    const uint32_t sQ = smem_u32(smattn);
    const uint32_t sKV = sQ + AQBYTES;     // stage s: K at s*ASTGB, V at +AKVB

    const int t = threadIdx.x, lane = t & 31, warp = t >> 5;
    const int b = blockIdx.z, h = blockIdx.y;
    const int q0 = blockIdx.x * ATQ;
    const size_t base = (size_t)b * SEQ * DMODEL + (size_t)h * HDIM;

    // prologue: Q (group), KV0 (group), KV1 (group)
#pragma unroll
    for (int i = 0; i < 4; i++) {
        int idx = t + i * 256, row = idx >> 3, ch = idx & 7;
        CP_ASYNC16(sQ + (uint32_t)(row * ASTR + ch * 8) * 2,
                   Q + base + (size_t)(q0 + row) * DMODEL + ch * 8);
    }
    CP_COMMIT();
#pragma unroll
    for (int p = 0; p < 2; p++) {
        const uint32_t bo = sKV + (uint32_t)p * ASTGB;
        const size_t kvb = base + (size_t)(p * ATKV) * DMODEL;
#pragma unroll
        for (int i = 0; i < 2; i++) {
            int idx = t + i * 256, row = idx >> 3, ch = idx & 7;
            CP_ASYNC16(bo + (uint32_t)(row * ASTR + ch * 8) * 2,
                       K + kvb + (size_t)row * DMODEL + ch * 8);
            CP_ASYNC16(bo + AKVB + (uint32_t)(row * ASTR + ch * 8) * 2,
                       V + kvb + (size_t)row * DMODEL + ch * 8);
        }
        CP_COMMIT();
    }

    CP_WAIT(2);            // Q done (KV0/KV1 may be pending)
    __syncthreads();

    // Q fragments, resident for the whole KV loop
    uint32_t qa[4][4];
    {
        const uint32_t aq = (uint32_t)((warp * 16 + (lane & 15)) * ASTR + ((lane >> 4) << 3));
#pragma unroll
        for (int kh = 0; kh < 4; kh++)
            ldmx4(sQ + (aq + kh * 16) * 2, qa[kh][0], qa[kh][1], qa[kh][2], qa[kh][3]);
    }

    float oacc[8][4];
#pragma unroll
    for (int j = 0; j < 8; j++)
#pragma unroll
        for (int e = 0; e < 4; e++) oacc[j][e] = 0.f;
    float m0 = -1e30f, m1 = -1e30f, l0 = 0.f, l1 = 0.f;

    const uint32_t koff = (uint32_t)((((lane >> 4) << 3) + (lane & 7)) * ASTR
                                     + (((lane >> 3) & 1) << 3));
    const uint32_t voff = (uint32_t)((lane & 15) * ASTR + ((lane >> 4) << 3));

    int buf = 0, nbuf = 2;
    for (int it = 0; it < NKV; it++) {
        if (it + 1 < NKV) { CP_WAIT(1); } else { CP_WAIT(0); }
        __syncthreads();
        if (it + 2 < NKV) {
            const uint32_t bo = sKV + (uint32_t)nbuf * ASTGB;
            const size_t kvb = base + (size_t)((it + 2) * ATKV) * DMODEL;
#pragma unroll
            for (int i = 0; i < 2; i++) {
                int idx = t + i * 256, row = idx >> 3, ch = idx & 7;
                CP_ASYNC16(bo + (uint32_t)(row * ASTR + ch * 8) * 2,
                           K + kvb + (size_t)row * DMODEL + ch * 8);
                CP_ASYNC16(bo + AKVB + (uint32_t)(row * ASTR + ch * 8) * 2,
                           V + kvb + (size_t)row * DMODEL + ch * 8);
            }
            CP_COMMIT();
            nbuf = (nbuf == 2) ? 0 : nbuf + 1;
        }

        const uint32_t kb = sKV + (uint32_t)buf * ASTGB;
        const uint32_t vb = kb + AKVB;
        buf = (buf == 2) ? 0 : buf + 1;

        // S = Q @ K^T  (warp: 16 x 64)
        float sacc[8][4];
#pragma unroll
        for (int j = 0; j < 8; j++)
#pragma unroll
            for (int e = 0; e < 4; e++) sacc[j][e] = 0.f;
#pragma unroll
        for (int kh = 0; kh < 4; kh++) {
#pragma unroll
            for (int j2 = 0; j2 < 4; j2++) {
                uint32_t r0, r1, r2, r3;
                ldmx4(kb + (koff + (uint32_t)(j2 * 16 * ASTR + kh * 16)) * 2, r0, r1, r2, r3);
                mma_bf16(sacc[j2*2],   qa[kh][0], qa[kh][1], qa[kh][2], qa[kh][3], r0, r1);
                mma_bf16(sacc[j2*2+1], qa[kh][0], qa[kh][1], qa[kh][2], qa[kh][3], r2, r3);
            }
        }

        // online softmax (fp32); rows r = 16*warp + lane>>2 and r+8
        float mx0 = m0, mx1 = m1;
#pragma unroll
        for (int j = 0; j < 8; j++) {
            mx0 = fmaxf(mx0, fmaxf(sacc[j][0], sacc[j][1]));
            mx1 = fmaxf(mx1, fmaxf(sacc[j][2], sacc[j][3]));
        }
        mx0 = fmaxf(mx0, __shfl_xor_sync(0xffffffffu, mx0, 1));
        mx0 = fmaxf(mx0, __shfl_xor_sync(0xffffffffu, mx0, 2));
        mx1 = fmaxf(mx1, __shfl_xor_sync(0xffffffffu, mx1, 1));
        mx1 = fmaxf(mx1, __shfl_xor_sync(0xffffffffu, mx1, 2));
        const float al0 = ex2((m0 - mx0) * CEXP);
        const float al1 = ex2((m1 - mx1) * CEXP);
        m0 = mx0; m1 = mx1;

        uint32_t pa[4][4];
        float rs0 = 0.f, rs1 = 0.f;
#pragma unroll
        for (int kk = 0; kk < 4; kk++) {
#pragma unroll
            for (int u = 0; u < 2; u++) {
                const int j = kk * 2 + u;
                float p0 = ex2((sacc[j][0] - mx0) * CEXP);
                float p1 = ex2((sacc[j][1] - mx0) * CEXP);
                float p2 = ex2((sacc[j][2] - mx1) * CEXP);
                float p3 = ex2((sacc[j][3] - mx1) * CEXP);
                rs0 += p0 + p1; rs1 += p2 + p3;
                pa[kk][u*2]     = pack_bf16(p0, p1);
                pa[kk][u*2 + 1] = pack_bf16(p2, p3);
            }
        }
        l0 = l0 * al0 + rs0;
        l1 = l1 * al1 + rs1;
#pragma unroll
        for (int j = 0; j < 8; j++) {
            oacc[j][0] *= al0; oacc[j][1] *= al0;
            oacc[j][2] *= al1; oacc[j][3] *= al1;
        }

        // O += P @ V
#pragma unroll
        for (int kk = 0; kk < 4; kk++) {
#pragma unroll
            for (int j2 = 0; j2 < 4; j2++) {
                uint32_t r0, r1, r2, r3;
                ldmx4t(vb + (voff + (uint32_t)(kk * 16 * ASTR + j2 * 16)) * 2, r0, r1, r2, r3);
                mma_bf16(oacc[j2*2],   pa[kk][0], pa[kk][1], pa[kk][2], pa[kk][3], r0, r1);
                mma_bf16(oacc[j2*2+1], pa[kk][0], pa[kk][1], pa[kk][2], pa[kk][3], r2, r3);
            }
        }
    }

    l0 += __shfl_xor_sync(0xffffffffu, l0, 1);
    l0 += __shfl_xor_sync(0xffffffffu, l0, 2);
    l1 += __shfl_xor_sync(0xffffffffu, l1, 1);
    l1 += __shfl_xor_sync(0xffffffffu, l1, 2);
    const float inv0 = 1.f / l0, inv1 = 1.f / l1;

    const int r = warp * 16 + (lane >> 2);
    __nv_bfloat16* o0 = O + (size_t)(b * SEQ + q0 + r) * DMODEL + h * HDIM + (lane & 3) * 2;
    __nv_bfloat16* o1 = o0 + (size_t)8 * DMODEL;
#pragma unroll
    for (int jn = 0; jn < 8; jn++) {
        *(__nv_bfloat162*)(o0 + jn * 8) =
            __floats2bfloat162_rn(oacc[jn][0] * inv0, oacc[jn][1] * inv0);
        *(__nv_bfloat162*)(o1 + jn * 8) =
            __floats2bfloat162_rn(oacc[jn][2] * inv1, oacc[jn][3] * inv1);
    }
}

// ---------------------------------------------------------------------------
// fp32 -> bf16 cast (elementwise, vectorized)
// ---------------------------------------------------------------------------
__global__ __launch_bounds__(256)
void cast_bf16(const float* __restrict__ in, __nv_bfloat16* __restrict__ out, int n4)
{
    int i = blockIdx.x * blockDim.x + threadIdx.x;
    if (i >= n4) return;
    float4 v = *(const float4*)(in + (size_t)i * 4);
    *(__nv_bfloat162*)(out + (size_t)i * 4)     = __floats2bfloat162_rn(v.x, v.y);
    *(__nv_bfloat162*)(out + (size_t)i * 4 + 2) = __floats2bfloat162_rn(v.z, v.w);
}

// ---------------------------------------------------------------------------
// Transpose + cast all 4 weights: in[K,N] fp32 -> out[N,K] bf16 (z selects).
// z in {0,1,2} -> g_wqkv + z*DMODEL*DMODEL, z=3 -> g_wpb.
// ---------------------------------------------------------------------------
__global__ __launch_bounds__(256)
void transpose_cast4(const float* __restrict__ w0, const float* __restrict__ w1,
                     const float* __restrict__ w2, const float* __restrict__ w3,
                     __nv_bfloat16* __restrict__ oqkv, __nv_bfloat16* __restrict__ op)
{
    const int z = blockIdx.z;
    const float* in  = (z == 0) ? w0 : (z == 1) ? w1 : (z == 2) ? w2 : w3;
    __nv_bfloat16* out = (z < 3) ? (oqkv + (size_t)z * DMODEL * DMODEL) : op;
    __shared__ float tile[32][33];
    const int n0 = blockIdx.x * 32;
    const int k0 = blockIdx.y * 32;
    const int tx = threadIdx.x & 31;
    const int ty = threadIdx.x >> 5;   // 0..7
#pragma unroll
    for (int i = 0; i < 32; i += 8)
        tile[ty + i][tx] = in[(size_t)(k0 + ty + i) * DMODEL + n0 + tx];
    __syncthreads();
#pragma unroll
    for (int i = 0; i < 32; i += 8)
        out[(size_t)(n0 + ty + i) * DMODEL + k0 + tx] = __float2bfloat16(tile[tx][ty + i]);
}

// ---------------------------------------------------------------------------
// LayerNorm: one block per row (1024 elems), 256 threads, eps = 1e-6
// ---------------------------------------------------------------------------
__global__ __launch_bounds__(256)
void ln_kernel(const float* __restrict__ Y, const float* __restrict__ gamma,
               const float* __restrict__ beta, float* __restrict__ out)
{
    const int row = blockIdx.x;
    const int t = threadIdx.x;
    const float* y = Y + (size_t)row * DMODEL;

    float4 v = *(const float4*)(y + t * 4);
    float s  = v.x + v.y + v.z + v.w;
    float ss = v.x*v.x + v.y*v.y + v.z*v.z + v.w*v.w;

    __shared__ float rs[8], rss[8];
    int lane = t & 31, wid = t >> 5;
#pragma unroll
    for (int o = 16; o > 0; o >>= 1) {
        s  += __shfl_xor_sync(0xffffffffu, s,  o);
        ss += __shfl_xor_sync(0xffffffffu, ss, o);
    }
    if (lane == 0) { rs[wid] = s; rss[wid] = ss; }
    __syncthreads();
    if (wid == 0) {
        s  = (lane < 8) ? rs[lane]  : 0.f;
        ss = (lane < 8) ? rss[lane] : 0.f;
#pragma unroll
        for (int o = 4; o > 0; o >>= 1) {
            s  += __shfl_xor_sync(0xffffffffu, s,  o);
            ss += __shfl_xor_sync(0xffffffffu, ss, o);
        }
        if (lane == 0) { rs[0] = s; rss[0] = ss; }
    }
    __syncthreads();

    float mean = rs[0] * (1.f / DMODEL);
    float var  = rss[0] * (1.f / DMODEL) - mean * mean;
    float rstd = rsqrtf(var + 1e-6f);

    float4 g  = *(const float4*)(gamma + t * 4);
    float4 be = *(const float4*)(beta  + t * 4);
    float4 r;
    r.x = (v.x - mean) * rstd * g.x + be.x;
    r.y = (v.y - mean) * rstd * g.y + be.y;
    r.z = (v.z - mean) * rstd * g.z + be.z;
    r.w = (v.w - mean) * rstd * g.w + be.w;
    *(float4*)(out + (size_t)row * DMODEL + t * 4) = r;
}

// ---------------------------------------------------------------------------
// Launch
// ---------------------------------------------------------------------------
extern "C" void kernel_launch(void* const* d_in, const int* in_sizes, int n_in,
                              void* d_out, int out_size)
{
    const float* x      = (const float*)d_in[0];
    const float* w_q    = (const float*)d_in[1];
    const float* w_k    = (const float*)d_in[2];
    const float* w_v    = (const float*)d_in[3];
    const float* w_proj = (const float*)d_in[4];
    const float* b_proj = (const float*)d_in[5];
    const float* gamma  = (const float*)d_in[6];
    const float* beta   = (const float*)d_in[7];
    float* out = (float*)d_out;

    float* y;
    __nv_bfloat16 *xb, *qkvb, *ob, *wqkv, *wpb;
    cudaGetSymbolAddress((void**)&y,    g_y);
    cudaGetSymbolAddress((void**)&xb,   g_xb);
    cudaGetSymbolAddress((void**)&qkvb, g_qkvb);
    cudaGetSymbolAddress((void**)&ob,   g_ob);
    cudaGetSymbolAddress((void**)&wqkv, g_wqkv);
    cudaGetSymbolAddress((void**)&wpb,  g_wpb);

    cudaFuncSetAttribute(gemm_mma<0>, cudaFuncAttributeMaxDynamicSharedMemorySize, GSMEM);
    cudaFuncSetAttribute(gemm_mma<1>, cudaFuncAttributeMaxDynamicSharedMemorySize, GSMEM);
    cudaFuncSetAttribute(attn_mma, cudaFuncAttributeMaxDynamicSharedMemorySize, ASMEM);

    // Casts / weight transposes
    const int n4 = MROWS * DMODEL / 4;
    cast_bf16<<<(n4 + 255) / 256, 256>>>(x, xb, n4);
    dim3 tg(DMODEL / 32, DMODEL / 32, 4);
    transpose_cast4<<<tg, 256>>>(w_q, w_k, w_v, w_proj, wqkv, wpb);

    // Fused QKV projection (bf16 out, split into q/k/v regions)
    dim3 gq(3 * DMODEL / BN, MROWS / BM);   // (24, 64)
    gemm_mma<0><<<gq, 256, GSMEM>>>(xb, wqkv, qkvb, nullptr, nullptr);

    // Flash attention on tensor cores
    dim3 ga(SEQ / ATQ, NHEAD, BATCH);       // (16, 16, 4)
    attn_mma<<<ga, 256, ASMEM>>>(qkvb, qkvb + (size_t)MROWS * DMODEL,
                                 qkvb + (size_t)2 * MROWS * DMODEL, ob);

    // proj + bias + residual (fp32 out)
    dim3 gp(DMODEL / BN, MROWS / BM);       // (8, 64)
    gemm_mma<1><<<gp, 256, GSMEM>>>(ob, wpb, y, b_proj, x);

    ln_kernel<<<MROWS, 256>>>(y, gamma, beta, out);
}